// round 2
// baseline (speedup 1.0000x reference)
#include <cuda_runtime.h>
#include <cstdint>

#define NN    40000
#define DH    128
#define DOUT  64

// ---------------- scratch (device globals; no allocation allowed) ----------------
__device__ __align__(16) float g_deg [NN];
__device__ __align__(16) float g_dinv[NN];
__device__ __align__(16) float g_hs1 [NN * DH];    // dinv-prescaled h1 = dinv * (x@W1)
__device__ __align__(16) float g_agg1[NN * DH];    // scatter accumulator, init = self term
__device__ __align__(16) float g_h1r [NN * DH];    // relu(layer1 output)
__device__ __align__(16) float g_hs2 [NN * DOUT];
__device__ __align__(16) float g_agg2[NN * DOUT];
__device__ int g_is64;                              // edge_index element width flag

// ---------------- packed fp32 reductions (sm_90+) ----------------
__device__ __forceinline__ void red_add_v4(float* a, float4 v) {
    asm volatile("red.global.add.v4.f32 [%0], {%1,%2,%3,%4};"
                 :: "l"(a), "f"(v.x), "f"(v.y), "f"(v.z), "f"(v.w) : "memory");
}
__device__ __forceinline__ void red_add_v2(float* a, float2 v) {
    asm volatile("red.global.add.v2.f32 [%0], {%1,%2};"
                 :: "l"(a), "f"(v.x), "f"(v.y) : "memory");
}

// ---------------- edge-index width detection ----------------
// int64 values < 40000: every odd 32-bit word is a zero high-half.
// int32 random indices: odd words are ~uniform in [0,40000) — 64 zeros impossible.
__global__ void k_detect(const int* __restrict__ ei32) {
    if (threadIdx.x == 0) {
        int zeros = 0;
        #pragma unroll
        for (int i = 1; i < 128; i += 2) zeros += (ei32[i] == 0);
        g_is64 = (zeros >= 48) ? 1 : 0;
    }
}

__device__ __forceinline__ void load_edge(const void* ei, int e, int E, int& s, int& d) {
    if (g_is64) {
        const long long* p = (const long long*)ei;
        s = (int)p[e]; d = (int)p[E + e];
    } else {
        const int* p = (const int*)ei;
        s = p[e]; d = p[E + e];
    }
}

// ---------------- degree / normalization ----------------
__global__ void k_deg_init() {
    int i = blockIdx.x * blockDim.x + threadIdx.x;
    if (i < NN) g_deg[i] = 1.0f;               // self-loop
}

__global__ void k_deg_count(const void* __restrict__ ei, int E) {
    int e = blockIdx.x * blockDim.x + threadIdx.x;
    if (e < E) {
        int s, d; load_edge(ei, e, E, s, d);
        if ((unsigned)d < NN) atomicAdd(&g_deg[d], 1.0f);
    }
}

__global__ void k_dinv() {
    int i = blockIdx.x * blockDim.x + threadIdx.x;
    if (i < NN) g_dinv[i] = rsqrtf(g_deg[i]);
}

// ---------------- fused GEMM + dinv prescale, writes hs and agg(=self term) ----------------
// X: [M,128] row-major, W: [128,N]. Tile: 64 rows/block.
template<int N, int LAYER>
__global__ void k_gemm_scale(const float* __restrict__ Xin, const float* __restrict__ W) {
    constexpr int K    = 128;
    constexpr int CPT  = 4;
    constexpr int CT   = N / CPT;     // 32 (N=128) or 16 (N=64)
    constexpr int RPT  = 8;
    constexpr int RT   = 8;
    constexpr int ROWS = RT * RPT;    // 64
    __shared__ float sX[ROWS * K];    // 32 KB

    const float* X   = (LAYER == 1) ? Xin : g_h1r;
    float*       hs  = (LAYER == 1) ? g_hs1  : g_hs2;
    float*       agg = (LAYER == 1) ? g_agg1 : g_agg2;

    const int tid      = threadIdx.x;
    const int nthreads = CT * RT;
    const int row0     = blockIdx.x * ROWS;

    const float4* xg = (const float4*)(X + (size_t)row0 * K);
    for (int idx = tid; idx < ROWS * K / 4; idx += nthreads)
        ((float4*)sX)[idx] = xg[idx];
    __syncthreads();

    const int c     = (tid % CT) * CPT;
    const int rbase = (tid / CT) * RPT;

    float acc[RPT][CPT];
    #pragma unroll
    for (int i = 0; i < RPT; i++)
        #pragma unroll
        for (int j = 0; j < CPT; j++) acc[i][j] = 0.0f;

    #pragma unroll 4
    for (int k = 0; k < K; k++) {
        float4 w = *(const float4*)(W + k * N + c);   // L1/L2-resident (W <= 64 KB)
        #pragma unroll
        for (int i = 0; i < RPT; i++) {
            float xv = sX[(rbase + i) * K + k];       // warp-broadcast LDS
            acc[i][0] += xv * w.x;
            acc[i][1] += xv * w.y;
            acc[i][2] += xv * w.z;
            acc[i][3] += xv * w.w;
        }
    }

    #pragma unroll
    for (int i = 0; i < RPT; i++) {
        int   r = row0 + rbase + i;
        float d = g_dinv[r];
        float4 v = make_float4(acc[i][0]*d, acc[i][1]*d, acc[i][2]*d, acc[i][3]*d);
        *(float4*)(hs  + (size_t)r * N + c) = v;
        *(float4*)(agg + (size_t)r * N + c) = v;   // self-loop contribution
    }
}

// ---------------- edge scatter: warp per edge ----------------
__global__ void k_scatter1(const void* __restrict__ ei, int E) {
    int warp = blockIdx.x * (blockDim.x >> 5) + (threadIdx.x >> 5);
    if (warp >= E) return;
    int lane = threadIdx.x & 31;
    int src, dst; load_edge(ei, warp, E, src, dst);
    if ((unsigned)src >= NN || (unsigned)dst >= NN) return;
    float4 v = ((const float4*)(g_hs1 + (size_t)src * DH))[lane];     // 128 f32 = 32 x float4
    red_add_v4((float*)(((float4*)(g_agg1 + (size_t)dst * DH)) + lane), v);
}

__global__ void k_scatter2(const void* __restrict__ ei, int E) {
    int warp = blockIdx.x * (blockDim.x >> 5) + (threadIdx.x >> 5);
    if (warp >= E) return;
    int lane = threadIdx.x & 31;
    int src, dst; load_edge(ei, warp, E, src, dst);
    if ((unsigned)src >= NN || (unsigned)dst >= NN) return;
    float2 v = ((const float2*)(g_hs2 + (size_t)src * DOUT))[lane];   // 64 f32 = 32 x float2
    red_add_v2((float*)(((float2*)(g_agg2 + (size_t)dst * DOUT)) + lane), v);
}

// ---------------- epilogues ----------------
__global__ void k_post1(const float* __restrict__ b1) {
    int i = blockIdx.x * blockDim.x + threadIdx.x;
    if (i < NN * DH) {
        int r = i >> 7;          // /128
        int j = i & 127;
        float v = g_agg1[i] * g_dinv[r] + b1[j];
        g_h1r[i] = v > 0.0f ? v : 0.0f;
    }
}

__global__ void k_post2(const float* __restrict__ b2, float* __restrict__ out) {
    int i = blockIdx.x * blockDim.x + threadIdx.x;
    if (i < NN * DOUT) {
        int r = i >> 6;          // /64
        int j = i & 63;
        out[i] = g_agg2[i] * g_dinv[r] + b2[j];
    }
}

// ---------------- launch ----------------
extern "C" void kernel_launch(void* const* d_in, const int* in_sizes, int n_in,
                              void* d_out, int out_size) {
    const float* x  = (const float*)d_in[0];
    const void*  ei = d_in[1];
    const float* W1 = (const float*)d_in[2];
    const float* b1 = (const float*)d_in[3];
    const float* W2 = (const float*)d_in[4];
    const float* b2 = (const float*)d_in[5];
    const int E = in_sizes[1] / 2;          // 640000 under both int32/int64 views

    k_detect   <<<1, 32>>>((const int*)ei);
    k_deg_init <<<(NN + 255) / 256, 256>>>();
    k_deg_count<<<(E  + 255) / 256, 256>>>(ei, E);
    k_dinv     <<<(NN + 255) / 256, 256>>>();

    // Layer 1
    k_gemm_scale<DH, 1><<<NN / 64, 32 * 8>>>(x, W1);
    k_scatter1<<<(E + 7) / 8, 256>>>(ei, E);
    k_post1<<<(NN * DH + 255) / 256, 256>>>(b1);

    // Layer 2
    k_gemm_scale<DOUT, 2><<<NN / 64, 16 * 8>>>(nullptr, W2);
    k_scatter2<<<(E + 7) / 8, 256>>>(ei, E);
    k_post2<<<(NN * DOUT + 255) / 256, 256>>>(b2, (float*)d_out);
}